// round 1
// baseline (speedup 1.0000x reference)
#include <cuda_runtime.h>

#define SEQ 4096
#define DIM 512
#define NH 8
#define HD 64
#define ATTN_SCALE 0.125f  // 1/sqrt(64)

// Scratch (allocation-free): Q, K, V, attention output, each [SEQ, DIM] fp32.
__device__ float g_q[SEQ * DIM];
__device__ float g_k[SEQ * DIM];
__device__ float g_v[SEQ * DIM];
__device__ float g_attn[SEQ * DIM];

// ---------------------------------------------------------------------------
// C[M,N] = A[M,K] * B[N,K]^T   with M=4096, N=K=512 (Linear: y = x @ W.T)
// 128x128 block tile, BK=16, 256 threads, 8x8 per-thread micro-tile.
// ---------------------------------------------------------------------------
__global__ __launch_bounds__(256) void sgemm_nt(const float* __restrict__ A,
                                                const float* __restrict__ B,
                                                float* __restrict__ C) {
    constexpr int BM = 128, BN = 128, BK = 16;
    __shared__ float As[BK][BM + 4];
    __shared__ float Bs[BK][BN + 4];
    const int bm = blockIdx.y * BM, bn = blockIdx.x * BN;
    const int tid = threadIdx.x;
    const int lr = tid >> 2;          // 0..63 : tile row (two passes cover 128)
    const int lc = (tid & 3) << 2;    // 0,4,8,12 : float col within BK
    const int ty = tid >> 4, tx = tid & 15;

    float acc[8][8];
#pragma unroll
    for (int i = 0; i < 8; i++)
#pragma unroll
        for (int j = 0; j < 8; j++) acc[i][j] = 0.f;

    for (int k0 = 0; k0 < DIM; k0 += BK) {
#pragma unroll
        for (int i = 0; i < 2; i++) {
            const int r = lr + (i << 6);
            float4 va = *(const float4*)(A + (bm + r) * DIM + k0 + lc);
            As[lc + 0][r] = va.x; As[lc + 1][r] = va.y;
            As[lc + 2][r] = va.z; As[lc + 3][r] = va.w;
            float4 vb = *(const float4*)(B + (bn + r) * DIM + k0 + lc);
            Bs[lc + 0][r] = vb.x; Bs[lc + 1][r] = vb.y;
            Bs[lc + 2][r] = vb.z; Bs[lc + 3][r] = vb.w;
        }
        __syncthreads();
#pragma unroll
        for (int kk = 0; kk < BK; kk++) {
            float a[8], b[8];
            *(float4*)&a[0] = *(const float4*)&As[kk][ty * 8];
            *(float4*)&a[4] = *(const float4*)&As[kk][ty * 8 + 4];
            *(float4*)&b[0] = *(const float4*)&Bs[kk][tx * 8];
            *(float4*)&b[4] = *(const float4*)&Bs[kk][tx * 8 + 4];
#pragma unroll
            for (int i = 0; i < 8; i++)
#pragma unroll
                for (int j = 0; j < 8; j++) acc[i][j] += a[i] * b[j];
        }
        __syncthreads();
    }
#pragma unroll
    for (int i = 0; i < 8; i++) {
        float* cp = C + (bm + ty * 8 + i) * DIM + bn + tx * 8;
        *(float4*)cp       = make_float4(acc[i][0], acc[i][1], acc[i][2], acc[i][3]);
        *(float4*)(cp + 4) = make_float4(acc[i][4], acc[i][5], acc[i][6], acc[i][7]);
    }
}

// ---------------------------------------------------------------------------
// Flash-attention style fused kernel. Q/K/V stored [SEQ, DIM]; head h lives
// in columns [h*64, h*64+64). Block = (64 queries, one head), loops over 64
// key tiles of 64 keys each with an online softmax.
// Thread layout: 256 threads as 16x16; thread (ty,tx) owns a 4q x 4(k|d)
// micro-tile. Row statistics reduced across the 16 tx lanes (half-warp).
// Shared memory: Qs[d][q] (transposed, pre-scaled), KP = union of Ks[d][k]
// and P[q][k], Vs[k][d]. 3 x 16 KB = 48 KB exactly.
// ---------------------------------------------------------------------------
__global__ __launch_bounds__(256) void flash_attn_kernel() {
    constexpr int BQ = 64, BKV = 64;
    __shared__ float Qs[HD][BQ];     // [d][q], pre-scaled by ATTN_SCALE
    __shared__ float KP[BKV][BQ];    // phase 1: Ks[d][k]; phase 2: P[q][k]
    __shared__ float Vs[BKV][HD];    // [k][d]

    const int h = blockIdx.y;
    const int q0 = blockIdx.x * BQ;
    const int tid = threadIdx.x;
    const int ty = tid >> 4, tx = tid & 15;
    const int lr = tid >> 2;         // loader row 0..63
    const int lcb = tid & 3;         // loader float4-col base

    // Load Q tile, transposed + scaled.
#pragma unroll
    for (int i = 0; i < 4; i++) {
        const int c = (lcb + 4 * i) * 4;
        float4 v = *(const float4*)(g_q + (q0 + lr) * DIM + h * HD + c);
        Qs[c + 0][lr] = v.x * ATTN_SCALE;
        Qs[c + 1][lr] = v.y * ATTN_SCALE;
        Qs[c + 2][lr] = v.z * ATTN_SCALE;
        Qs[c + 3][lr] = v.w * ATTN_SCALE;
    }

    float m[4], l[4], o[4][4];
#pragma unroll
    for (int i = 0; i < 4; i++) {
        m[i] = -1e30f; l[i] = 0.f;
#pragma unroll
        for (int j = 0; j < 4; j++) o[i][j] = 0.f;
    }

    for (int j0 = 0; j0 < SEQ; j0 += BKV) {
        __syncthreads();  // previous iteration's readers of KP/Vs are done
#pragma unroll
        for (int i = 0; i < 4; i++) {
            const int c = (lcb + 4 * i) * 4;
            float4 kv = *(const float4*)(g_k + (j0 + lr) * DIM + h * HD + c);
            KP[c + 0][lr] = kv.x; KP[c + 1][lr] = kv.y;   // K transposed [d][k]
            KP[c + 2][lr] = kv.z; KP[c + 3][lr] = kv.w;
            float4 vv = *(const float4*)(g_v + (j0 + lr) * DIM + h * HD + c);
            *(float4*)&Vs[lr][c] = vv;                     // V natural [k][d]
        }
        __syncthreads();

        // S = (Q*scale) @ K^T for this tile, 4x4 per thread.
        float s[4][4];
#pragma unroll
        for (int i = 0; i < 4; i++)
#pragma unroll
            for (int j = 0; j < 4; j++) s[i][j] = 0.f;
#pragma unroll
        for (int d = 0; d < HD; d++) {
            float a[4], b[4];
            *(float4*)a = *(const float4*)&Qs[d][ty * 4];
            *(float4*)b = *(const float4*)&KP[d][tx * 4];
#pragma unroll
            for (int i = 0; i < 4; i++)
#pragma unroll
                for (int j = 0; j < 4; j++) s[i][j] += a[i] * b[j];
        }

        // Online softmax update (rows reduced across 16 tx lanes).
#pragma unroll
        for (int i = 0; i < 4; i++) {
            float mx = fmaxf(fmaxf(s[i][0], s[i][1]), fmaxf(s[i][2], s[i][3]));
#pragma unroll
            for (int off = 1; off < 16; off <<= 1)
                mx = fmaxf(mx, __shfl_xor_sync(0xffffffffu, mx, off));
            const float mnew = fmaxf(m[i], mx);
            const float corr = __expf(m[i] - mnew);
            float rsum = 0.f;
#pragma unroll
            for (int j = 0; j < 4; j++) {
                s[i][j] = __expf(s[i][j] - mnew);
                rsum += s[i][j];
            }
#pragma unroll
            for (int off = 1; off < 16; off <<= 1)
                rsum += __shfl_xor_sync(0xffffffffu, rsum, off);
            l[i] = l[i] * corr + rsum;
            m[i] = mnew;
#pragma unroll
            for (int j = 0; j < 4; j++) o[i][j] *= corr;
        }

        __syncthreads();  // all S reads of KP (as K) complete
        // Write P into KP as [q][k].
#pragma unroll
        for (int i = 0; i < 4; i++)
            *(float4*)&KP[ty * 4 + i][tx * 4] =
                make_float4(s[i][0], s[i][1], s[i][2], s[i][3]);
        __syncthreads();

        // O += P @ V  (thread owns q rows ty*4.., d cols tx*4..)
#pragma unroll
        for (int k = 0; k < BKV; k++) {
            float b[4];
            *(float4*)b = *(const float4*)&Vs[k][tx * 4];
#pragma unroll
            for (int i = 0; i < 4; i++) {
                const float a = KP[ty * 4 + i][k];
#pragma unroll
                for (int j = 0; j < 4; j++) o[i][j] += a * b[j];
            }
        }
    }

    // Epilogue: normalize and write [S, D] layout for the output projection.
#pragma unroll
    for (int i = 0; i < 4; i++) {
        const float inv = 1.0f / l[i];
        float4 r = make_float4(o[i][0] * inv, o[i][1] * inv,
                               o[i][2] * inv, o[i][3] * inv);
        *(float4*)(g_attn + (q0 + ty * 4 + i) * DIM + h * HD + tx * 4) = r;
    }
}

// ---------------------------------------------------------------------------
extern "C" void kernel_launch(void* const* d_in, const int* in_sizes, int n_in,
                              void* d_out, int out_size) {
    const float* x  = (const float*)d_in[0];
    const float* Wq = (const float*)d_in[1];
    const float* Wk = (const float*)d_in[2];
    const float* Wv = (const float*)d_in[3];
    const float* Wo = (const float*)d_in[4];
    float* out = (float*)d_out;

    float *qp, *kp, *vp, *ap;
    cudaGetSymbolAddress((void**)&qp, g_q);
    cudaGetSymbolAddress((void**)&kp, g_k);
    cudaGetSymbolAddress((void**)&vp, g_v);
    cudaGetSymbolAddress((void**)&ap, g_attn);

    dim3 gemm_grid(DIM / 128, SEQ / 128);  // (4, 32)
    sgemm_nt<<<gemm_grid, 256>>>(x, Wq, qp);
    sgemm_nt<<<gemm_grid, 256>>>(x, Wk, kp);
    sgemm_nt<<<gemm_grid, 256>>>(x, Wv, vp);

    flash_attn_kernel<<<dim3(SEQ / 64, NH), 256>>>();

    sgemm_nt<<<gemm_grid, 256>>>(ap, Wo, out);
}

// round 2
// speedup vs baseline: 2.2492x; 2.2492x over previous
#include <cuda_runtime.h>
#include <cstdint>

#define SEQ 4096
#define DIM 512
#define NH 8
#define HD 64
// (1/sqrt(64)) * log2(e): lets softmax use exp2 throughout.
#define QK_SCALE 0.18033688011112042f

// Scratch (allocation-free): Q, K, V, attention output, each [SEQ, DIM] fp32.
__device__ float g_q[SEQ * DIM];
__device__ float g_k[SEQ * DIM];
__device__ float g_v[SEQ * DIM];
__device__ float g_attn[SEQ * DIM];

// ---------------------------------------------------------------------------
// fp32 SGEMM (unchanged from R1): C[M,N] = A[M,K] * B[N,K]^T, M=4096, N=K=512.
// ---------------------------------------------------------------------------
__global__ __launch_bounds__(256) void sgemm_nt(const float* __restrict__ A,
                                                const float* __restrict__ B,
                                                float* __restrict__ C) {
    constexpr int BM = 128, BN = 128, BK = 16;
    __shared__ float As[BK][BM + 4];
    __shared__ float Bs[BK][BN + 4];
    const int bm = blockIdx.y * BM, bn = blockIdx.x * BN;
    const int tid = threadIdx.x;
    const int lr = tid >> 2;
    const int lc = (tid & 3) << 2;
    const int ty = tid >> 4, tx = tid & 15;

    float acc[8][8];
#pragma unroll
    for (int i = 0; i < 8; i++)
#pragma unroll
        for (int j = 0; j < 8; j++) acc[i][j] = 0.f;

    for (int k0 = 0; k0 < DIM; k0 += BK) {
#pragma unroll
        for (int i = 0; i < 2; i++) {
            const int r = lr + (i << 6);
            float4 va = *(const float4*)(A + (bm + r) * DIM + k0 + lc);
            As[lc + 0][r] = va.x; As[lc + 1][r] = va.y;
            As[lc + 2][r] = va.z; As[lc + 3][r] = va.w;
            float4 vb = *(const float4*)(B + (bn + r) * DIM + k0 + lc);
            Bs[lc + 0][r] = vb.x; Bs[lc + 1][r] = vb.y;
            Bs[lc + 2][r] = vb.z; Bs[lc + 3][r] = vb.w;
        }
        __syncthreads();
#pragma unroll
        for (int kk = 0; kk < BK; kk++) {
            float a[8], b[8];
            *(float4*)&a[0] = *(const float4*)&As[kk][ty * 8];
            *(float4*)&a[4] = *(const float4*)&As[kk][ty * 8 + 4];
            *(float4*)&b[0] = *(const float4*)&Bs[kk][tx * 8];
            *(float4*)&b[4] = *(const float4*)&Bs[kk][tx * 8 + 4];
#pragma unroll
            for (int i = 0; i < 8; i++)
#pragma unroll
                for (int j = 0; j < 8; j++) acc[i][j] += a[i] * b[j];
        }
        __syncthreads();
    }
#pragma unroll
    for (int i = 0; i < 8; i++) {
        float* cp = C + (bm + ty * 8 + i) * DIM + bn + tx * 8;
        *(float4*)cp       = make_float4(acc[i][0], acc[i][1], acc[i][2], acc[i][3]);
        *(float4*)(cp + 4) = make_float4(acc[i][4], acc[i][5], acc[i][6], acc[i][7]);
    }
}

// ---------------------------------------------------------------------------
// tf32 tensor-core flash attention.
// Block: 128 queries x 1 head, 256 threads (8 warps). Warp w owns query rows
// [w*16, w*16+16) -> online softmax is warp-local (quad shuffles).
// mma.sync.m16n8k8.row.col tf32:
//   A frag: a0=(g,tig) a1=(g+8,tig) a2=(g,tig+4) a3=(g+8,tig+4)
//   B frag: b0=B[tig][g] b1=B[tig+4][g]   (B is k x n)
//   C frag: c0=(g,2tig) c1=(g,2tig+1) c2=(g+8,2tig) c3=(g+8,2tig+1)
// S = Q K^T: B(k=d, n=key) = K[key][d]  -> K in NATURAL layout, stride 72.
// O = P V  : B(k=key, n=d) = V[key][d]  -> V in NATURAL layout, stride 72.
// P stored warp-private, stride 68 -> conflict-free A-frag reloads.
// Shared: K 64x72 + V 64x72 + P 128x68 = 71680 B (P doubles as Q staging).
// ---------------------------------------------------------------------------
__device__ __forceinline__ uint32_t f2tf32(float x) {
    uint32_t r;
    asm("cvt.rna.tf32.f32 %0, %1;" : "=r"(r) : "f"(x));
    return r;
}

__device__ __forceinline__ void mma_tf32(float* d, const uint32_t* a,
                                         const uint32_t* b, const float* c) {
    asm volatile(
        "mma.sync.aligned.m16n8k8.row.col.f32.tf32.tf32.f32 "
        "{%0,%1,%2,%3}, {%4,%5,%6,%7}, {%8,%9}, {%10,%11,%12,%13};\n"
        : "=f"(d[0]), "=f"(d[1]), "=f"(d[2]), "=f"(d[3])
        : "r"(a[0]), "r"(a[1]), "r"(a[2]), "r"(a[3]),
          "r"(b[0]), "r"(b[1]),
          "f"(c[0]), "f"(c[1]), "f"(c[2]), "f"(c[3]));
}

#define KV_STRIDE 72
#define P_STRIDE 68
#define SMEM_FLOATS (2 * 64 * KV_STRIDE + 128 * P_STRIDE)  // 17920 floats

__global__ __launch_bounds__(256, 2) void flash_attn_tf32() {
    extern __shared__ float smem[];
    float* Ks = smem;                      // [64][72]
    float* Vs = smem + 64 * KV_STRIDE;     // [64][72]
    float* Ps = smem + 2 * 64 * KV_STRIDE; // [128][68]; Q staging first

    const int h   = blockIdx.y;
    const int q0  = blockIdx.x * 128;
    const int tid = threadIdx.x;
    const int warp = tid >> 5, lane = tid & 31;
    const int g = lane >> 2, tig = lane & 3;
    const int m0 = warp * 16;

    // ---- Stage Q tile (scaled + tf32) into Ps, then build register frags.
#pragma unroll
    for (int i = 0; i < 8; i++) {
        const int idx = tid + i * 256;          // 2048 float4s
        const int row = idx >> 4, c4 = (idx & 15) << 2;
        float4 v = *(const float4*)(g_q + (q0 + row) * DIM + h * HD + c4);
        float4 t;
        t.x = __uint_as_float(f2tf32(v.x * QK_SCALE));
        t.y = __uint_as_float(f2tf32(v.y * QK_SCALE));
        t.z = __uint_as_float(f2tf32(v.z * QK_SCALE));
        t.w = __uint_as_float(f2tf32(v.w * QK_SCALE));
        *(float4*)(Ps + row * P_STRIDE + c4) = t;
    }
    __syncthreads();

    uint32_t qa[8][4];
#pragma unroll
    for (int ks = 0; ks < 8; ks++) {
        const float* p = Ps + ks * 8;
        qa[ks][0] = __float_as_uint(p[(m0 + g) * P_STRIDE + tig]);
        qa[ks][1] = __float_as_uint(p[(m0 + g + 8) * P_STRIDE + tig]);
        qa[ks][2] = __float_as_uint(p[(m0 + g) * P_STRIDE + tig + 4]);
        qa[ks][3] = __float_as_uint(p[(m0 + g + 8) * P_STRIDE + tig + 4]);
    }

    float o[8][4];
#pragma unroll
    for (int nt = 0; nt < 8; nt++)
#pragma unroll
        for (int j = 0; j < 4; j++) o[nt][j] = 0.f;
    float mr0 = -1e30f, mr1 = -1e30f, l0 = 0.f, l1 = 0.f;

    for (int j0 = 0; j0 < SEQ; j0 += 64) {
        __syncthreads();  // prior K/V readers (and Q-frag builders) done
        // ---- Load K, V tiles (natural layout, tf32-converted).
#pragma unroll
        for (int i = 0; i < 4; i++) {
            const int idx = tid + i * 256;      // 1024 float4s each
            const int row = idx >> 4, c4 = (idx & 15) << 2;
            float4 kv = *(const float4*)(g_k + (j0 + row) * DIM + h * HD + c4);
            float4 tk;
            tk.x = __uint_as_float(f2tf32(kv.x));
            tk.y = __uint_as_float(f2tf32(kv.y));
            tk.z = __uint_as_float(f2tf32(kv.z));
            tk.w = __uint_as_float(f2tf32(kv.w));
            *(float4*)(Ks + row * KV_STRIDE + c4) = tk;
            float4 vv = *(const float4*)(g_v + (j0 + row) * DIM + h * HD + c4);
            float4 tv;
            tv.x = __uint_as_float(f2tf32(vv.x));
            tv.y = __uint_as_float(f2tf32(vv.y));
            tv.z = __uint_as_float(f2tf32(vv.z));
            tv.w = __uint_as_float(f2tf32(vv.w));
            *(float4*)(Vs + row * KV_STRIDE + c4) = tv;
        }
        __syncthreads();

        // ---- S = Qscaled @ K^T  (16 x 64 per warp)
        float s[8][4];
#pragma unroll
        for (int nt = 0; nt < 8; nt++)
#pragma unroll
            for (int j = 0; j < 4; j++) s[nt][j] = 0.f;
#pragma unroll
        for (int ks = 0; ks < 8; ks++) {
#pragma unroll
            for (int nt = 0; nt < 8; nt++) {
                uint32_t b[2];
                const float* kb = Ks + (nt * 8 + g) * KV_STRIDE + ks * 8 + tig;
                b[0] = __float_as_uint(kb[0]);
                b[1] = __float_as_uint(kb[4]);
                mma_tf32(s[nt], qa[ks], b, s[nt]);
            }
        }

        // ---- Online softmax (rows g and g+8 within warp, quad reduce).
        float mx0 = -1e30f, mx1 = -1e30f;
#pragma unroll
        for (int nt = 0; nt < 8; nt++) {
            mx0 = fmaxf(mx0, fmaxf(s[nt][0], s[nt][1]));
            mx1 = fmaxf(mx1, fmaxf(s[nt][2], s[nt][3]));
        }
        mx0 = fmaxf(mx0, __shfl_xor_sync(0xffffffffu, mx0, 1));
        mx0 = fmaxf(mx0, __shfl_xor_sync(0xffffffffu, mx0, 2));
        mx1 = fmaxf(mx1, __shfl_xor_sync(0xffffffffu, mx1, 1));
        mx1 = fmaxf(mx1, __shfl_xor_sync(0xffffffffu, mx1, 2));
        const float mn0 = fmaxf(mr0, mx0), mn1 = fmaxf(mr1, mx1);
        const float c0 = exp2f(mr0 - mn0), c1 = exp2f(mr1 - mn1);
        float rs0 = 0.f, rs1 = 0.f;
#pragma unroll
        for (int nt = 0; nt < 8; nt++) {
            s[nt][0] = exp2f(s[nt][0] - mn0);
            s[nt][1] = exp2f(s[nt][1] - mn0);
            s[nt][2] = exp2f(s[nt][2] - mn1);
            s[nt][3] = exp2f(s[nt][3] - mn1);
            rs0 += s[nt][0] + s[nt][1];
            rs1 += s[nt][2] + s[nt][3];
        }
        rs0 += __shfl_xor_sync(0xffffffffu, rs0, 1);
        rs0 += __shfl_xor_sync(0xffffffffu, rs0, 2);
        rs1 += __shfl_xor_sync(0xffffffffu, rs1, 1);
        rs1 += __shfl_xor_sync(0xffffffffu, rs1, 2);
        l0 = l0 * c0 + rs0; l1 = l1 * c1 + rs1;
        mr0 = mn0; mr1 = mn1;
#pragma unroll
        for (int nt = 0; nt < 8; nt++) {
            o[nt][0] *= c0; o[nt][1] *= c0;
            o[nt][2] *= c1; o[nt][3] *= c1;
        }

        // ---- Store P (tf32) to warp-private region.
        __syncwarp();
#pragma unroll
        for (int nt = 0; nt < 8; nt++) {
            float2 p0 = make_float2(__uint_as_float(f2tf32(s[nt][0])),
                                    __uint_as_float(f2tf32(s[nt][1])));
            float2 p1 = make_float2(__uint_as_float(f2tf32(s[nt][2])),
                                    __uint_as_float(f2tf32(s[nt][3])));
            *(float2*)(Ps + (m0 + g) * P_STRIDE + nt * 8 + 2 * tig) = p0;
            *(float2*)(Ps + (m0 + g + 8) * P_STRIDE + nt * 8 + 2 * tig) = p1;
        }
        __syncwarp();

        // ---- O += P @ V
#pragma unroll
        for (int ks = 0; ks < 8; ks++) {
            uint32_t a[4];
            const float* pp = Ps + ks * 8;
            a[0] = __float_as_uint(pp[(m0 + g) * P_STRIDE + tig]);
            a[1] = __float_as_uint(pp[(m0 + g + 8) * P_STRIDE + tig]);
            a[2] = __float_as_uint(pp[(m0 + g) * P_STRIDE + tig + 4]);
            a[3] = __float_as_uint(pp[(m0 + g + 8) * P_STRIDE + tig + 4]);
#pragma unroll
            for (int nt = 0; nt < 8; nt++) {
                uint32_t b[2];
                const float* vb = Vs + (ks * 8 + tig) * KV_STRIDE + nt * 8 + g;
                b[0] = __float_as_uint(vb[0]);
                b[1] = __float_as_uint(vb[4 * KV_STRIDE]);
                mma_tf32(o[nt], a, b, o[nt]);
            }
        }
    }

    // ---- Epilogue: normalize, write [S, D] for the output projection.
    const float inv0 = 1.f / l0, inv1 = 1.f / l1;
#pragma unroll
    for (int nt = 0; nt < 8; nt++) {
        float* d0 = g_attn + (q0 + m0 + g) * DIM + h * HD + nt * 8 + 2 * tig;
        float* d1 = g_attn + (q0 + m0 + g + 8) * DIM + h * HD + nt * 8 + 2 * tig;
        *(float2*)d0 = make_float2(o[nt][0] * inv0, o[nt][1] * inv0);
        *(float2*)d1 = make_float2(o[nt][2] * inv1, o[nt][3] * inv1);
    }
}

// ---------------------------------------------------------------------------
extern "C" void kernel_launch(void* const* d_in, const int* in_sizes, int n_in,
                              void* d_out, int out_size) {
    const float* x  = (const float*)d_in[0];
    const float* Wq = (const float*)d_in[1];
    const float* Wk = (const float*)d_in[2];
    const float* Wv = (const float*)d_in[3];
    const float* Wo = (const float*)d_in[4];
    float* out = (float*)d_out;

    float *qp, *kp, *vp, *ap;
    cudaGetSymbolAddress((void**)&qp, g_q);
    cudaGetSymbolAddress((void**)&kp, g_k);
    cudaGetSymbolAddress((void**)&vp, g_v);
    cudaGetSymbolAddress((void**)&ap, g_attn);

    dim3 gemm_grid(DIM / 128, SEQ / 128);  // (4, 32)
    sgemm_nt<<<gemm_grid, 256>>>(x, Wq, qp);
    sgemm_nt<<<gemm_grid, 256>>>(x, Wk, kp);
    sgemm_nt<<<gemm_grid, 256>>>(x, Wv, vp);

    const int smem_bytes = SMEM_FLOATS * sizeof(float);  // 71680
    cudaFuncSetAttribute(flash_attn_tf32,
                         cudaFuncAttributeMaxDynamicSharedMemorySize, smem_bytes);
    flash_attn_tf32<<<dim3(SEQ / 128, NH), 256, smem_bytes>>>();

    sgemm_nt<<<gemm_grid, 256>>>(ap, Wo, out);
}

// round 4
// speedup vs baseline: 3.1931x; 1.4197x over previous
#include <cuda_runtime.h>
#include <cstdint>

#define SEQ 4096
#define DIM 512
#define NH 8
#define HD 64
// (1/sqrt(64)) * log2(e): lets softmax use exp2 throughout.
#define QK_SCALE 0.18033688011112042f

// Scratch (allocation-free): Q, K, V, attention output, each [SEQ, DIM] fp32.
__device__ float g_q[SEQ * DIM];
__device__ float g_k[SEQ * DIM];
__device__ float g_v[SEQ * DIM];
__device__ float g_attn[SEQ * DIM];

// ---------------------------------------------------------------------------
// tf32 helpers (same fragment mappings proven in the R2 flash kernel).
// ---------------------------------------------------------------------------
__device__ __forceinline__ uint32_t f2tf32(float x) {
    uint32_t r;
    asm("cvt.rna.tf32.f32 %0, %1;" : "=r"(r) : "f"(x));
    return r;
}

__device__ __forceinline__ void mma_tf32(float* d, const uint32_t* a,
                                         const uint32_t* b, const float* c) {
    asm volatile(
        "mma.sync.aligned.m16n8k8.row.col.f32.tf32.tf32.f32 "
        "{%0,%1,%2,%3}, {%4,%5,%6,%7}, {%8,%9}, {%10,%11,%12,%13};\n"
        : "=f"(d[0]), "=f"(d[1]), "=f"(d[2]), "=f"(d[3])
        : "r"(a[0]), "r"(a[1]), "r"(a[2]), "r"(a[3]),
          "r"(b[0]), "r"(b[1]),
          "f"(c[0]), "f"(c[1]), "f"(c[2]), "f"(c[3]));
}

// ---------------------------------------------------------------------------
// tf32 tensor-core GEMM: C[M,N] = A[M,K] * B[N,K]^T  (M=4096, N=K=512).
// Block tile 128x128, BK=32, 256 threads (8 warps as 4x2).
// Warp tile 32(M) x 64(N): B-fragments loaded once, shared by 2 m-groups.
// Identical mma addressing to the flash kernel's S = Q K^T phase.
// ---------------------------------------------------------------------------
#define GS 36  // smem row stride (pad 32 -> 36 floats: conflict-free frags)

__device__ __forceinline__ void gemm_tile_tf32(const float* __restrict__ A,
                                               const float* __restrict__ B,
                                               float* __restrict__ C,
                                               int bm, int bn, float* smem) {
    float* As = smem;             // [128][36]
    float* Bs = smem + 128 * GS;  // [128][36]
    const int tid = threadIdx.x;
    const int warp = tid >> 5, lane = tid & 31;
    const int g = lane >> 2, tig = lane & 3;
    const int m0 = (warp >> 1) * 32;   // warp rows [m0, m0+32)
    const int n0 = (warp & 1) * 64;    // warp cols [n0, n0+64)

    float acc[2][8][4];
#pragma unroll
    for (int mi = 0; mi < 2; mi++)
#pragma unroll
        for (int nt = 0; nt < 8; nt++)
#pragma unroll
            for (int j = 0; j < 4; j++) acc[mi][nt][j] = 0.f;

    for (int k0 = 0; k0 < DIM; k0 += 32) {
        __syncthreads();
        // Fill As, Bs (tf32-converted). 1024 float4 each; 4 per thread.
#pragma unroll
        for (int i = 0; i < 4; i++) {
            const int idx = tid + i * 256;
            const int row = idx >> 3, c4 = (idx & 7) << 2;
            float4 va = *(const float4*)(A + (bm + row) * DIM + k0 + c4);
            float4 ta;
            ta.x = __uint_as_float(f2tf32(va.x));
            ta.y = __uint_as_float(f2tf32(va.y));
            ta.z = __uint_as_float(f2tf32(va.z));
            ta.w = __uint_as_float(f2tf32(va.w));
            *(float4*)(As + row * GS + c4) = ta;
            float4 vb = *(const float4*)(B + (bn + row) * DIM + k0 + c4);
            float4 tb;
            tb.x = __uint_as_float(f2tf32(vb.x));
            tb.y = __uint_as_float(f2tf32(vb.y));
            tb.z = __uint_as_float(f2tf32(vb.z));
            tb.w = __uint_as_float(f2tf32(vb.w));
            *(float4*)(Bs + row * GS + c4) = tb;
        }
        __syncthreads();

#pragma unroll
        for (int ks = 0; ks < 4; ks++) {
            uint32_t a[2][4];
#pragma unroll
            for (int mi = 0; mi < 2; mi++) {
                const float* ap = As + (m0 + mi * 16) * GS + ks * 8;
                a[mi][0] = __float_as_uint(ap[g * GS + tig]);
                a[mi][1] = __float_as_uint(ap[(g + 8) * GS + tig]);
                a[mi][2] = __float_as_uint(ap[g * GS + tig + 4]);
                a[mi][3] = __float_as_uint(ap[(g + 8) * GS + tig + 4]);
            }
#pragma unroll
            for (int nt = 0; nt < 8; nt++) {
                uint32_t b[2];
                const float* bp = Bs + (n0 + nt * 8 + g) * GS + ks * 8 + tig;
                b[0] = __float_as_uint(bp[0]);
                b[1] = __float_as_uint(bp[4]);
                mma_tf32(acc[0][nt], a[0], b, acc[0][nt]);
                mma_tf32(acc[1][nt], a[1], b, acc[1][nt]);
            }
        }
    }

    // Epilogue: c0=(g,2tig) c1=(g,2tig+1) c2=(g+8,2tig) c3=(g+8,2tig+1)
#pragma unroll
    for (int mi = 0; mi < 2; mi++)
#pragma unroll
        for (int nt = 0; nt < 8; nt++) {
            float* d0 = C + (bm + m0 + mi * 16 + g) * DIM + bn + n0 + nt * 8 + 2 * tig;
            float* d1 = d0 + 8 * DIM;
            *(float2*)d0 = make_float2(acc[mi][nt][0], acc[mi][nt][1]);
            *(float2*)d1 = make_float2(acc[mi][nt][2], acc[mi][nt][3]);
        }
}

#define GEMM_SMEM (2 * 128 * GS * sizeof(float))  // 36864 B

// Fused QKV: grid (12, 32). blockIdx.x -> {weight, n-tile}.
__global__ __launch_bounds__(256, 2) void qkv_gemm_tf32(
    const float* __restrict__ x,
    const float* __restrict__ Wq, const float* __restrict__ Wk,
    const float* __restrict__ Wv,
    float* __restrict__ q, float* __restrict__ k, float* __restrict__ v) {
    extern __shared__ float smem[];
    const int w = blockIdx.x >> 2;
    const int bn = (blockIdx.x & 3) * 128;
    const int bm = blockIdx.y * 128;
    const float* B = (w == 0) ? Wq : (w == 1) ? Wk : Wv;
    float* C = (w == 0) ? q : (w == 1) ? k : v;
    gemm_tile_tf32(x, B, C, bm, bn, smem);
}

__global__ __launch_bounds__(256, 2) void out_gemm_tf32(
    const float* __restrict__ A, const float* __restrict__ B,
    float* __restrict__ C) {
    extern __shared__ float smem[];
    gemm_tile_tf32(A, B, C, blockIdx.y * 128, blockIdx.x * 128, smem);
}

// ---------------------------------------------------------------------------
// tf32 tensor-core flash attention (unchanged from R2; see R2 notes).
// ---------------------------------------------------------------------------
#define KV_STRIDE 72
#define P_STRIDE 68
#define SMEM_FLOATS (2 * 64 * KV_STRIDE + 128 * P_STRIDE)  // 17920 floats

__global__ __launch_bounds__(256, 2) void flash_attn_tf32() {
    extern __shared__ float smem[];
    float* Ks = smem;                      // [64][72]
    float* Vs = smem + 64 * KV_STRIDE;     // [64][72]
    float* Ps = smem + 2 * 64 * KV_STRIDE; // [128][68]; Q staging first

    const int h   = blockIdx.y;
    const int q0  = blockIdx.x * 128;
    const int tid = threadIdx.x;
    const int warp = tid >> 5, lane = tid & 31;
    const int g = lane >> 2, tig = lane & 3;
    const int m0 = warp * 16;

#pragma unroll
    for (int i = 0; i < 8; i++) {
        const int idx = tid + i * 256;
        const int row = idx >> 4, c4 = (idx & 15) << 2;
        float4 v = *(const float4*)(g_q + (q0 + row) * DIM + h * HD + c4);
        float4 t;
        t.x = __uint_as_float(f2tf32(v.x * QK_SCALE));
        t.y = __uint_as_float(f2tf32(v.y * QK_SCALE));
        t.z = __uint_as_float(f2tf32(v.z * QK_SCALE));
        t.w = __uint_as_float(f2tf32(v.w * QK_SCALE));
        *(float4*)(Ps + row * P_STRIDE + c4) = t;
    }
    __syncthreads();

    uint32_t qa[8][4];
#pragma unroll
    for (int ks = 0; ks < 8; ks++) {
        const float* p = Ps + ks * 8;
        qa[ks][0] = __float_as_uint(p[(m0 + g) * P_STRIDE + tig]);
        qa[ks][1] = __float_as_uint(p[(m0 + g + 8) * P_STRIDE + tig]);
        qa[ks][2] = __float_as_uint(p[(m0 + g) * P_STRIDE + tig + 4]);
        qa[ks][3] = __float_as_uint(p[(m0 + g + 8) * P_STRIDE + tig + 4]);
    }

    float o[8][4];
#pragma unroll
    for (int nt = 0; nt < 8; nt++)
#pragma unroll
        for (int j = 0; j < 4; j++) o[nt][j] = 0.f;
    float mr0 = -1e30f, mr1 = -1e30f, l0 = 0.f, l1 = 0.f;

    for (int j0 = 0; j0 < SEQ; j0 += 64) {
        __syncthreads();
#pragma unroll
        for (int i = 0; i < 4; i++) {
            const int idx = tid + i * 256;
            const int row = idx >> 4, c4 = (idx & 15) << 2;
            float4 kv = *(const float4*)(g_k + (j0 + row) * DIM + h * HD + c4);
            float4 tk;
            tk.x = __uint_as_float(f2tf32(kv.x));
            tk.y = __uint_as_float(f2tf32(kv.y));
            tk.z = __uint_as_float(f2tf32(kv.z));
            tk.w = __uint_as_float(f2tf32(kv.w));
            *(float4*)(Ks + row * KV_STRIDE + c4) = tk;
            float4 vv = *(const float4*)(g_v + (j0 + row) * DIM + h * HD + c4);
            float4 tv;
            tv.x = __uint_as_float(f2tf32(vv.x));
            tv.y = __uint_as_float(f2tf32(vv.y));
            tv.z = __uint_as_float(f2tf32(vv.z));
            tv.w = __uint_as_float(f2tf32(vv.w));
            *(float4*)(Vs + row * KV_STRIDE + c4) = tv;
        }
        __syncthreads();

        float s[8][4];
#pragma unroll
        for (int nt = 0; nt < 8; nt++)
#pragma unroll
            for (int j = 0; j < 4; j++) s[nt][j] = 0.f;
#pragma unroll
        for (int ks = 0; ks < 8; ks++) {
#pragma unroll
            for (int nt = 0; nt < 8; nt++) {
                uint32_t b[2];
                const float* kb = Ks + (nt * 8 + g) * KV_STRIDE + ks * 8 + tig;
                b[0] = __float_as_uint(kb[0]);
                b[1] = __float_as_uint(kb[4]);
                mma_tf32(s[nt], qa[ks], b, s[nt]);
            }
        }

        float mx0 = -1e30f, mx1 = -1e30f;
#pragma unroll
        for (int nt = 0; nt < 8; nt++) {
            mx0 = fmaxf(mx0, fmaxf(s[nt][0], s[nt][1]));
            mx1 = fmaxf(mx1, fmaxf(s[nt][2], s[nt][3]));
        }
        mx0 = fmaxf(mx0, __shfl_xor_sync(0xffffffffu, mx0, 1));
        mx0 = fmaxf(mx0, __shfl_xor_sync(0xffffffffu, mx0, 2));
        mx1 = fmaxf(mx1, __shfl_xor_sync(0xffffffffu, mx1, 1));
        mx1 = fmaxf(mx1, __shfl_xor_sync(0xffffffffu, mx1, 2));
        const float mn0 = fmaxf(mr0, mx0), mn1 = fmaxf(mr1, mx1);
        const float c0 = exp2f(mr0 - mn0), c1 = exp2f(mr1 - mn1);
        float rs0 = 0.f, rs1 = 0.f;
#pragma unroll
        for (int nt = 0; nt < 8; nt++) {
            s[nt][0] = exp2f(s[nt][0] - mn0);
            s[nt][1] = exp2f(s[nt][1] - mn0);
            s[nt][2] = exp2f(s[nt][2] - mn1);
            s[nt][3] = exp2f(s[nt][3] - mn1);
            rs0 += s[nt][0] + s[nt][1];
            rs1 += s[nt][2] + s[nt][3];
        }
        rs0 += __shfl_xor_sync(0xffffffffu, rs0, 1);
        rs0 += __shfl_xor_sync(0xffffffffu, rs0, 2);
        rs1 += __shfl_xor_sync(0xffffffffu, rs1, 1);
        rs1 += __shfl_xor_sync(0xffffffffu, rs1, 2);
        l0 = l0 * c0 + rs0; l1 = l1 * c1 + rs1;
        mr0 = mn0; mr1 = mn1;
#pragma unroll
        for (int nt = 0; nt < 8; nt++) {
            o[nt][0] *= c0; o[nt][1] *= c0;
            o[nt][2] *= c1; o[nt][3] *= c1;
        }

        __syncwarp();
#pragma unroll
        for (int nt = 0; nt < 8; nt++) {
            float2 p0 = make_float2(__uint_as_float(f2tf32(s[nt][0])),
                                    __uint_as_float(f2tf32(s[nt][1])));
            float2 p1 = make_float2(__uint_as_float(f2tf32(s[nt][2])),
                                    __uint_as_float(f2tf32(s[nt][3])));
            *(float2*)(Ps + (m0 + g) * P_STRIDE + nt * 8 + 2 * tig) = p0;
            *(float2*)(Ps + (m0 + g + 8) * P_STRIDE + nt * 8 + 2 * tig) = p1;
        }
        __syncwarp();

#pragma unroll
        for (int ks = 0; ks < 8; ks++) {
            uint32_t a[4];
            const float* pp = Ps + ks * 8;
            a[0] = __float_as_uint(pp[(m0 + g) * P_STRIDE + tig]);
            a[1] = __float_as_uint(pp[(m0 + g + 8) * P_STRIDE + tig]);
            a[2] = __float_as_uint(pp[(m0 + g) * P_STRIDE + tig + 4]);
            a[3] = __float_as_uint(pp[(m0 + g + 8) * P_STRIDE + tig + 4]);
#pragma unroll
            for (int nt = 0; nt < 8; nt++) {
                uint32_t b[2];
                const float* vb = Vs + (ks * 8 + tig) * KV_STRIDE + nt * 8 + g;
                b[0] = __float_as_uint(vb[0]);
                b[1] = __float_as_uint(vb[4 * KV_STRIDE]);
                mma_tf32(o[nt], a, b, o[nt]);
            }
        }
    }

    const float inv0 = 1.f / l0, inv1 = 1.f / l1;
#pragma unroll
    for (int nt = 0; nt < 8; nt++) {
        float* d0 = g_attn + (q0 + m0 + g) * DIM + h * HD + nt * 8 + 2 * tig;
        float* d1 = g_attn + (q0 + m0 + g + 8) * DIM + h * HD + nt * 8 + 2 * tig;
        *(float2*)d0 = make_float2(o[nt][0] * inv0, o[nt][1] * inv0);
        *(float2*)d1 = make_float2(o[nt][2] * inv1, o[nt][3] * inv1);
    }
}

// ---------------------------------------------------------------------------
extern "C" void kernel_launch(void* const* d_in, const int* in_sizes, int n_in,
                              void* d_out, int out_size) {
    const float* x  = (const float*)d_in[0];
    const float* Wq = (const float*)d_in[1];
    const float* Wk = (const float*)d_in[2];
    const float* Wv = (const float*)d_in[3];
    const float* Wo = (const float*)d_in[4];
    float* out = (float*)d_out;

    float *qp, *kp, *vp, *ap;
    cudaGetSymbolAddress((void**)&qp, g_q);
    cudaGetSymbolAddress((void**)&kp, g_k);
    cudaGetSymbolAddress((void**)&vp, g_v);
    cudaGetSymbolAddress((void**)&ap, g_attn);

    // Idempotent, host-side only: safe on every call (no static guards).
    cudaFuncSetAttribute(qkv_gemm_tf32,
                         cudaFuncAttributeMaxDynamicSharedMemorySize, GEMM_SMEM);
    cudaFuncSetAttribute(out_gemm_tf32,
                         cudaFuncAttributeMaxDynamicSharedMemorySize, GEMM_SMEM);
    cudaFuncSetAttribute(flash_attn_tf32,
                         cudaFuncAttributeMaxDynamicSharedMemorySize,
                         SMEM_FLOATS * sizeof(float));

    qkv_gemm_tf32<<<dim3(12, SEQ / 128), 256, GEMM_SMEM>>>(x, Wq, Wk, Wv,
                                                           qp, kp, vp);

    flash_attn_tf32<<<dim3(SEQ / 128, NH), 256,
                      SMEM_FLOATS * sizeof(float)>>>();

    out_gemm_tf32<<<dim3(DIM / 128, SEQ / 128), 256, GEMM_SMEM>>>(ap, Wo, out);
}

// round 5
// speedup vs baseline: 3.8034x; 1.1911x over previous
#include <cuda_runtime.h>
#include <cstdint>

#define SEQ 4096
#define DIM 512
#define NH 8
#define HD 64
// (1/sqrt(64)) * log2(e): lets softmax use exp2 throughout.
#define QK_SCALE 0.18033688011112042f

// Scratch (allocation-free): Q, K, V, attention output, each [SEQ, DIM] fp32.
__device__ float g_q[SEQ * DIM];
__device__ float g_k[SEQ * DIM];
__device__ float g_v[SEQ * DIM];
__device__ float g_attn[SEQ * DIM];

// ---------------------------------------------------------------------------
// tf32 helpers.
// ---------------------------------------------------------------------------
__device__ __forceinline__ uint32_t f2tf32(float x) {
    uint32_t r;
    asm("cvt.rna.tf32.f32 %0, %1;" : "=r"(r) : "f"(x));
    return r;
}

__device__ __forceinline__ void mma_tf32(float* d, const uint32_t* a,
                                         const uint32_t* b, const float* c) {
    asm volatile(
        "mma.sync.aligned.m16n8k8.row.col.f32.tf32.tf32.f32 "
        "{%0,%1,%2,%3}, {%4,%5,%6,%7}, {%8,%9}, {%10,%11,%12,%13};\n"
        : "=f"(d[0]), "=f"(d[1]), "=f"(d[2]), "=f"(d[3])
        : "r"(a[0]), "r"(a[1]), "r"(a[2]), "r"(a[3]),
          "r"(b[0]), "r"(b[1]),
          "f"(c[0]), "f"(c[1]), "f"(c[2]), "f"(c[3]));
}

// ---------------------------------------------------------------------------
// tf32 tensor-core GEMM (unchanged from R4): C[M,N] = A[M,K]*B[N,K]^T.
// ---------------------------------------------------------------------------
#define GS 36

__device__ __forceinline__ void gemm_tile_tf32(const float* __restrict__ A,
                                               const float* __restrict__ B,
                                               float* __restrict__ C,
                                               int bm, int bn, float* smem) {
    float* As = smem;
    float* Bs = smem + 128 * GS;
    const int tid = threadIdx.x;
    const int warp = tid >> 5, lane = tid & 31;
    const int g = lane >> 2, tig = lane & 3;
    const int m0 = (warp >> 1) * 32;
    const int n0 = (warp & 1) * 64;

    float acc[2][8][4];
#pragma unroll
    for (int mi = 0; mi < 2; mi++)
#pragma unroll
        for (int nt = 0; nt < 8; nt++)
#pragma unroll
            for (int j = 0; j < 4; j++) acc[mi][nt][j] = 0.f;

    for (int k0 = 0; k0 < DIM; k0 += 32) {
        __syncthreads();
#pragma unroll
        for (int i = 0; i < 4; i++) {
            const int idx = tid + i * 256;
            const int row = idx >> 3, c4 = (idx & 7) << 2;
            float4 va = *(const float4*)(A + (bm + row) * DIM + k0 + c4);
            float4 ta;
            ta.x = __uint_as_float(f2tf32(va.x));
            ta.y = __uint_as_float(f2tf32(va.y));
            ta.z = __uint_as_float(f2tf32(va.z));
            ta.w = __uint_as_float(f2tf32(va.w));
            *(float4*)(As + row * GS + c4) = ta;
            float4 vb = *(const float4*)(B + (bn + row) * DIM + k0 + c4);
            float4 tb;
            tb.x = __uint_as_float(f2tf32(vb.x));
            tb.y = __uint_as_float(f2tf32(vb.y));
            tb.z = __uint_as_float(f2tf32(vb.z));
            tb.w = __uint_as_float(f2tf32(vb.w));
            *(float4*)(Bs + row * GS + c4) = tb;
        }
        __syncthreads();

#pragma unroll
        for (int ks = 0; ks < 4; ks++) {
            uint32_t a[2][4];
#pragma unroll
            for (int mi = 0; mi < 2; mi++) {
                const float* ap = As + (m0 + mi * 16) * GS + ks * 8;
                a[mi][0] = __float_as_uint(ap[g * GS + tig]);
                a[mi][1] = __float_as_uint(ap[(g + 8) * GS + tig]);
                a[mi][2] = __float_as_uint(ap[g * GS + tig + 4]);
                a[mi][3] = __float_as_uint(ap[(g + 8) * GS + tig + 4]);
            }
#pragma unroll
            for (int nt = 0; nt < 8; nt++) {
                uint32_t b[2];
                const float* bp = Bs + (n0 + nt * 8 + g) * GS + ks * 8 + tig;
                b[0] = __float_as_uint(bp[0]);
                b[1] = __float_as_uint(bp[4]);
                mma_tf32(acc[0][nt], a[0], b, acc[0][nt]);
                mma_tf32(acc[1][nt], a[1], b, acc[1][nt]);
            }
        }
    }

#pragma unroll
    for (int mi = 0; mi < 2; mi++)
#pragma unroll
        for (int nt = 0; nt < 8; nt++) {
            float* d0 = C + (bm + m0 + mi * 16 + g) * DIM + bn + n0 + nt * 8 + 2 * tig;
            float* d1 = d0 + 8 * DIM;
            *(float2*)d0 = make_float2(acc[mi][nt][0], acc[mi][nt][1]);
            *(float2*)d1 = make_float2(acc[mi][nt][2], acc[mi][nt][3]);
        }
}

#define GEMM_SMEM (2 * 128 * GS * sizeof(float))  // 36864 B

__global__ __launch_bounds__(256, 2) void qkv_gemm_tf32(
    const float* __restrict__ x,
    const float* __restrict__ Wq, const float* __restrict__ Wk,
    const float* __restrict__ Wv,
    float* __restrict__ q, float* __restrict__ k, float* __restrict__ v) {
    extern __shared__ float smem[];
    const int w = blockIdx.x >> 2;
    const int bn = (blockIdx.x & 3) * 128;
    const int bm = blockIdx.y * 128;
    const float* B = (w == 0) ? Wq : (w == 1) ? Wk : Wv;
    float* C = (w == 0) ? q : (w == 1) ? k : v;
    gemm_tile_tf32(x, B, C, bm, bn, smem);
}

__global__ __launch_bounds__(256, 2) void out_gemm_tf32(
    const float* __restrict__ A, const float* __restrict__ B,
    float* __restrict__ C) {
    extern __shared__ float smem[];
    gemm_tile_tf32(A, B, C, blockIdx.y * 128, blockIdx.x * 128, smem);
}

// ---------------------------------------------------------------------------
// tf32 flash attention, v2: 4 warps x 32 query rows (2 m-groups per warp).
//  - Ks stride 68 (bank = 4g+tig, conflict-free B-frags; 72 had 2-way).
//  - Vs stride 72 (bank = 8tig+g, conflict-free).
//  - Q fragments resident in registers (qa[8][2][4]); Ps is the P buffer.
//  - P rows are warp-private -> __syncwarp ordering only.
// Shared: Ks 64x68 + Vs 64x72 + Ps 128x68 = 17664 floats = 70656 B.
// ---------------------------------------------------------------------------
#define KST 68
#define VST 72
#define PST 68
#define FA_SMEM_FLOATS (64 * KST + 64 * VST + 128 * PST)

__global__ __launch_bounds__(128, 2) void flash_attn_tf32() {
    extern __shared__ float smem[];
    float* Ks = smem;                          // [64][68]
    float* Vs = smem + 64 * KST;               // [64][72]
    float* Ps = smem + 64 * KST + 64 * VST;    // [128][68]; Q staging first

    const int h   = blockIdx.y;
    const int q0  = blockIdx.x * 128;
    const int tid = threadIdx.x;
    const int warp = tid >> 5, lane = tid & 31;
    const int g = lane >> 2, tig = lane & 3;
    const int m0 = warp * 32;

    // ---- Stage Q tile (scaled + tf32) into Ps; 2048 float4 / 128 threads.
#pragma unroll
    for (int i = 0; i < 16; i++) {
        const int idx = tid + i * 128;
        const int row = idx >> 4, c4 = (idx & 15) << 2;
        float4 v = *(const float4*)(g_q + (q0 + row) * DIM + h * HD + c4);
        float4 t;
        t.x = __uint_as_float(f2tf32(v.x * QK_SCALE));
        t.y = __uint_as_float(f2tf32(v.y * QK_SCALE));
        t.z = __uint_as_float(f2tf32(v.z * QK_SCALE));
        t.w = __uint_as_float(f2tf32(v.w * QK_SCALE));
        *(float4*)(Ps + row * PST + c4) = t;
    }
    __syncthreads();

    // Q fragments -> registers (warp-local rows; Ps rows m0..m0+31).
    uint32_t qa[8][2][4];
#pragma unroll
    for (int ks = 0; ks < 8; ks++)
#pragma unroll
        for (int mi = 0; mi < 2; mi++) {
            const float* p = Ps + (m0 + mi * 16) * PST + ks * 8;
            qa[ks][mi][0] = __float_as_uint(p[g * PST + tig]);
            qa[ks][mi][1] = __float_as_uint(p[(g + 8) * PST + tig]);
            qa[ks][mi][2] = __float_as_uint(p[g * PST + tig + 4]);
            qa[ks][mi][3] = __float_as_uint(p[(g + 8) * PST + tig + 4]);
        }

    float o[2][8][4];
#pragma unroll
    for (int mi = 0; mi < 2; mi++)
#pragma unroll
        for (int nt = 0; nt < 8; nt++)
#pragma unroll
            for (int j = 0; j < 4; j++) o[mi][nt][j] = 0.f;
    float mr[2][2] = {{-1e30f, -1e30f}, {-1e30f, -1e30f}};
    float l[2][2] = {{0.f, 0.f}, {0.f, 0.f}};

    for (int j0 = 0; j0 < SEQ; j0 += 64) {
        __syncthreads();  // prior tile's K/V readers done
        // ---- Fill K (stride 68), V (stride 72): 1024 float4 each / 128 thr.
#pragma unroll
        for (int i = 0; i < 8; i++) {
            const int idx = tid + i * 128;
            const int row = idx >> 4, c4 = (idx & 15) << 2;
            float4 kv = *(const float4*)(g_k + (j0 + row) * DIM + h * HD + c4);
            float4 tk;
            tk.x = __uint_as_float(f2tf32(kv.x));
            tk.y = __uint_as_float(f2tf32(kv.y));
            tk.z = __uint_as_float(f2tf32(kv.z));
            tk.w = __uint_as_float(f2tf32(kv.w));
            *(float4*)(Ks + row * KST + c4) = tk;
            float4 vv = *(const float4*)(g_v + (j0 + row) * DIM + h * HD + c4);
            float4 tv;
            tv.x = __uint_as_float(f2tf32(vv.x));
            tv.y = __uint_as_float(f2tf32(vv.y));
            tv.z = __uint_as_float(f2tf32(vv.z));
            tv.w = __uint_as_float(f2tf32(vv.w));
            *(float4*)(Vs + row * VST + c4) = tv;
        }
        __syncthreads();

        // ---- S = Qscaled @ K^T  (32 x 64 per warp)
        float s[2][8][4];
#pragma unroll
        for (int mi = 0; mi < 2; mi++)
#pragma unroll
            for (int nt = 0; nt < 8; nt++)
#pragma unroll
                for (int j = 0; j < 4; j++) s[mi][nt][j] = 0.f;
#pragma unroll
        for (int ks = 0; ks < 8; ks++) {
#pragma unroll
            for (int nt = 0; nt < 8; nt++) {
                uint32_t b[2];
                const float* kb = Ks + (nt * 8 + g) * KST + ks * 8 + tig;
                b[0] = __float_as_uint(kb[0]);
                b[1] = __float_as_uint(kb[4]);
                mma_tf32(s[0][nt], qa[ks][0], b, s[0][nt]);
                mma_tf32(s[1][nt], qa[ks][1], b, s[1][nt]);
            }
        }

        // ---- Online softmax per m-group (quad reduce).
#pragma unroll
        for (int mi = 0; mi < 2; mi++) {
            float mx0 = -1e30f, mx1 = -1e30f;
#pragma unroll
            for (int nt = 0; nt < 8; nt++) {
                mx0 = fmaxf(mx0, fmaxf(s[mi][nt][0], s[mi][nt][1]));
                mx1 = fmaxf(mx1, fmaxf(s[mi][nt][2], s[mi][nt][3]));
            }
            mx0 = fmaxf(mx0, __shfl_xor_sync(0xffffffffu, mx0, 1));
            mx0 = fmaxf(mx0, __shfl_xor_sync(0xffffffffu, mx0, 2));
            mx1 = fmaxf(mx1, __shfl_xor_sync(0xffffffffu, mx1, 1));
            mx1 = fmaxf(mx1, __shfl_xor_sync(0xffffffffu, mx1, 2));
            const float mn0 = fmaxf(mr[mi][0], mx0);
            const float mn1 = fmaxf(mr[mi][1], mx1);
            const float c0 = exp2f(mr[mi][0] - mn0);
            const float c1 = exp2f(mr[mi][1] - mn1);
            float rs0 = 0.f, rs1 = 0.f;
#pragma unroll
            for (int nt = 0; nt < 8; nt++) {
                s[mi][nt][0] = exp2f(s[mi][nt][0] - mn0);
                s[mi][nt][1] = exp2f(s[mi][nt][1] - mn0);
                s[mi][nt][2] = exp2f(s[mi][nt][2] - mn1);
                s[mi][nt][3] = exp2f(s[mi][nt][3] - mn1);
                rs0 += s[mi][nt][0] + s[mi][nt][1];
                rs1 += s[mi][nt][2] + s[mi][nt][3];
            }
            rs0 += __shfl_xor_sync(0xffffffffu, rs0, 1);
            rs0 += __shfl_xor_sync(0xffffffffu, rs0, 2);
            rs1 += __shfl_xor_sync(0xffffffffu, rs1, 1);
            rs1 += __shfl_xor_sync(0xffffffffu, rs1, 2);
            l[mi][0] = l[mi][0] * c0 + rs0;
            l[mi][1] = l[mi][1] * c1 + rs1;
            mr[mi][0] = mn0; mr[mi][1] = mn1;
#pragma unroll
            for (int nt = 0; nt < 8; nt++) {
                o[mi][nt][0] *= c0; o[mi][nt][1] *= c0;
                o[mi][nt][2] *= c1; o[mi][nt][3] *= c1;
            }
        }

        // ---- Store P (tf32) to warp-private rows of Ps.
        __syncwarp();
#pragma unroll
        for (int mi = 0; mi < 2; mi++)
#pragma unroll
            for (int nt = 0; nt < 8; nt++) {
                float2 p0 = make_float2(__uint_as_float(f2tf32(s[mi][nt][0])),
                                        __uint_as_float(f2tf32(s[mi][nt][1])));
                float2 p1 = make_float2(__uint_as_float(f2tf32(s[mi][nt][2])),
                                        __uint_as_float(f2tf32(s[mi][nt][3])));
                float* pr = Ps + (m0 + mi * 16) * PST + nt * 8 + 2 * tig;
                *(float2*)(pr + g * PST) = p0;
                *(float2*)(pr + (g + 8) * PST) = p1;
            }
        __syncwarp();

        // ---- O += P @ V
#pragma unroll
        for (int ks = 0; ks < 8; ks++) {
            uint32_t a[2][4];
#pragma unroll
            for (int mi = 0; mi < 2; mi++) {
                const float* pp = Ps + (m0 + mi * 16) * PST + ks * 8;
                a[mi][0] = __float_as_uint(pp[g * PST + tig]);
                a[mi][1] = __float_as_uint(pp[(g + 8) * PST + tig]);
                a[mi][2] = __float_as_uint(pp[g * PST + tig + 4]);
                a[mi][3] = __float_as_uint(pp[(g + 8) * PST + tig + 4]);
            }
#pragma unroll
            for (int nt = 0; nt < 8; nt++) {
                uint32_t b[2];
                const float* vb = Vs + (ks * 8 + tig) * VST + nt * 8 + g;
                b[0] = __float_as_uint(vb[0]);
                b[1] = __float_as_uint(vb[4 * VST]);
                mma_tf32(o[0][nt], a[0], b, o[0][nt]);
                mma_tf32(o[1][nt], a[1], b, o[1][nt]);
            }
        }
    }

    // ---- Epilogue: normalize, write [S, D].
#pragma unroll
    for (int mi = 0; mi < 2; mi++) {
        const float inv0 = 1.f / l[mi][0], inv1 = 1.f / l[mi][1];
#pragma unroll
        for (int nt = 0; nt < 8; nt++) {
            float* d0 = g_attn + (q0 + m0 + mi * 16 + g) * DIM + h * HD + nt * 8 + 2 * tig;
            float* d1 = d0 + 8 * DIM;
            *(float2*)d0 = make_float2(o[mi][nt][0] * inv0, o[mi][nt][1] * inv0);
            *(float2*)d1 = make_float2(o[mi][nt][2] * inv1, o[mi][nt][3] * inv1);
        }
    }
}

// ---------------------------------------------------------------------------
extern "C" void kernel_launch(void* const* d_in, const int* in_sizes, int n_in,
                              void* d_out, int out_size) {
    const float* x  = (const float*)d_in[0];
    const float* Wq = (const float*)d_in[1];
    const float* Wk = (const float*)d_in[2];
    const float* Wv = (const float*)d_in[3];
    const float* Wo = (const float*)d_in[4];
    float* out = (float*)d_out;

    float *qp, *kp, *vp, *ap;
    cudaGetSymbolAddress((void**)&qp, g_q);
    cudaGetSymbolAddress((void**)&kp, g_k);
    cudaGetSymbolAddress((void**)&vp, g_v);
    cudaGetSymbolAddress((void**)&ap, g_attn);

    // Idempotent, host-side only: safe on every call.
    cudaFuncSetAttribute(qkv_gemm_tf32,
                         cudaFuncAttributeMaxDynamicSharedMemorySize, GEMM_SMEM);
    cudaFuncSetAttribute(out_gemm_tf32,
                         cudaFuncAttributeMaxDynamicSharedMemorySize, GEMM_SMEM);
    cudaFuncSetAttribute(flash_attn_tf32,
                         cudaFuncAttributeMaxDynamicSharedMemorySize,
                         FA_SMEM_FLOATS * sizeof(float));

    qkv_gemm_tf32<<<dim3(12, SEQ / 128), 256, GEMM_SMEM>>>(x, Wq, Wk, Wv,
                                                           qp, kp, vp);

    flash_attn_tf32<<<dim3(SEQ / 128, NH), 128,
                      FA_SMEM_FLOATS * sizeof(float)>>>();

    out_gemm_tf32<<<dim3(DIM / 128, SEQ / 128), 256, GEMM_SMEM>>>(ap, Wo, out);
}